// round 5
// baseline (speedup 1.0000x reference)
#include <cuda_runtime.h>
#include <cstdint>
#include <cstddef>

// Problem constants (match reference)
#define NMAX 100000
#define EMAX 1600000
#define K_DIM 128

// ---- Scratch (device globals; no allocations allowed) ----
__device__ int   g_deg[NMAX];
__device__ int   g_rowptr[NMAX + 1];
__device__ int   g_fill[NMAX];
__device__ int   g_col[EMAX];
__device__ float g_xl[(size_t)NMAX * 128];   // aggregated-path transform
__device__ float g_xr[(size_t)NMAX * 128];   // self-path transform (+bias)
__device__ float g_h[(size_t)NMAX * 128];    // layer-0 output
__device__ float g_h2[(size_t)NMAX * 128];   // layer-1 output

// ============================================================
// CSR build (counting sort by dst), rebuilt every launch
// ============================================================
__global__ void hist_k(const int* __restrict__ dst, int e) {
    int i = blockIdx.x * blockDim.x + threadIdx.x;
    if (i < e) atomicAdd(&g_deg[dst[i]], 1);
}

__global__ __launch_bounds__(1024) void scan_k(int n) {
    __shared__ int part[1024];
    int tid = threadIdx.x;
    int chunk = (n + 1023) >> 10;
    int beg = tid * chunk;
    int end = min(beg + chunk, n);
    int s = 0;
    for (int i = beg; i < end; i++) s += g_deg[i];
    part[tid] = s;
    __syncthreads();
    for (int off = 1; off < 1024; off <<= 1) {
        int v = (tid >= off) ? part[tid - off] : 0;
        __syncthreads();
        part[tid] += v;
        __syncthreads();
    }
    int base = part[tid] - s;  // exclusive prefix
    for (int i = beg; i < end; i++) {
        g_rowptr[i] = base;
        g_fill[i]   = base;
        base += g_deg[i];
    }
    if (tid == 1023) g_rowptr[n] = part[1023];
}

__global__ void scatter_k(const int* __restrict__ src, const int* __restrict__ dst, int e) {
    int i = blockIdx.x * blockDim.x + threadIdx.x;
    if (i < e) {
        int p = atomicAdd(&g_fill[dst[i]], 1);
        g_col[p] = src[i];
    }
}

// ============================================================
// tf32 / cp.async helpers
// ============================================================
__device__ __forceinline__ uint32_t f2tf(float x) {
    uint32_t u;
    asm("cvt.rna.tf32.f32 %0, %1;" : "=r"(u) : "f"(x));
    return u;
}

__device__ __forceinline__ void mma_tf32(
    float c[4], uint32_t a0, uint32_t a1, uint32_t a2, uint32_t a3,
    uint32_t b0, uint32_t b1)
{
    asm volatile(
        "mma.sync.aligned.m16n8k8.row.col.f32.tf32.tf32.f32 "
        "{%0,%1,%2,%3}, {%4,%5,%6,%7}, {%8,%9}, {%0,%1,%2,%3};"
        : "+f"(c[0]), "+f"(c[1]), "+f"(c[2]), "+f"(c[3])
        : "r"(a0), "r"(a1), "r"(a2), "r"(a3), "r"(b0), "r"(b1));
}

__device__ __forceinline__ uint32_t smem_u32(const void* p) {
    return (uint32_t)__cvta_generic_to_shared(p);
}

__device__ __forceinline__ void cp_async16(uint32_t dst, const void* src, int srcbytes) {
    asm volatile("cp.async.cg.shared.global [%0], [%1], 16, %2;"
                 :: "r"(dst), "l"(src), "r"(srcbytes));
}
__device__ __forceinline__ void cp_commit() {
    asm volatile("cp.async.commit_group;" ::: "memory");
}
template <int N>
__device__ __forceinline__ void cp_wait() {
    asm volatile("cp.async.wait_group %0;" :: "n"(N) : "memory");
}

// ============================================================
// Persistent dual GEMM (tf32 tensor cores), weights fully smem-resident:
//   Cl = A @ Wl ; Cr = A @ Wr + bias
// Grid = #SMs blocks; each block stages Wl+Wr ONCE (tf32), then loops over
// strided 64-row A-tiles, double-buffered via cp.async (raw fp32; A-frags
// converted with cvt.rna after LDS — numerics identical to staged-cvt).
// 8 warps: warp = (rowgrp 0..3 of 16 rows) x (n-half 0..1).
// ============================================================
template <int DOUT>
__global__ __launch_bounds__(256) void gemm_persist(
    const float* __restrict__ A,
    const float* __restrict__ Wl, const float* __restrict__ Wr,
    const float* __restrict__ bias,
    float* __restrict__ Cl, float* __restrict__ Cr, int n)
{
    constexpr int BM = 64;
    constexpr int AS_STRIDE = K_DIM + 4;   // 132 (floats)
    constexpr int BS_STRIDE = DOUT + 4;
    constexpr int NF = DOUT / 16;          // n-frags per warp (half of DOUT / 8)

    extern __shared__ uint32_t smraw[];
    // Ws[2][128][BS_STRIDE] then As[2][64][AS_STRIDE]
    uint32_t (*Ws)[K_DIM][BS_STRIDE] = (uint32_t(*)[K_DIM][BS_STRIDE])smraw;
    uint32_t (*As)[BM][AS_STRIDE] =
        (uint32_t(*)[BM][AS_STRIDE])(smraw + 2 * K_DIM * BS_STRIDE);

    const int tid = threadIdx.x;
    const int nTiles = (n + BM - 1) / BM;

    // ---- issue cp.async for this block's first tile ----
    int tile0 = blockIdx.x;
    {
        const int r  = tid >> 5;              // 0..63  (wait: 256 threads -> idx loop)
        // 64 rows x 32 float4 = 2048 chunks / 256 threads = 8 per thread
        for (int v = 0; v < 8; v++) {
            int idx = tid + v * 256;
            int rr  = idx >> 5;
            int kq  = (idx & 31) * 4;
            int gr  = tile0 * BM + rr;
            bool ok = (tile0 < nTiles) && (gr < n);
            const float* src = ok ? (A + (size_t)gr * K_DIM + kq) : A;
            cp_async16(smem_u32(&As[0][rr][kq]), src, ok ? 16 : 0);
        }
        (void)r;
    }
    cp_commit();

    // ---- stage Wl, Wr once (tf32) ----
    constexpr int WV = (K_DIM * DOUT) / (4 * 256);
    for (int w = 0; w < 2; w++) {
        const float* W = w ? Wr : Wl;
#pragma unroll
        for (int v = 0; v < WV; v++) {
            int idx = tid + v * 256;
            int kk  = idx / (DOUT / 4);
            int c4  = (idx % (DOUT / 4)) * 4;
            float4 bv = *(const float4*)(W + (size_t)kk * DOUT + c4);
            uint4 uv;
            uv.x = f2tf(bv.x); uv.y = f2tf(bv.y);
            uv.z = f2tf(bv.z); uv.w = f2tf(bv.w);
            *(uint4*)&Ws[w][kk][c4] = uv;
        }
    }

    const int warp = tid >> 5;
    const int lane = tid & 31;
    const int g    = lane >> 2;
    const int tig  = lane & 3;
    const int rgrp = warp & 3;          // row group of 16
    const int nh   = warp >> 2;         // n half
    const int wrow = rgrp * 16;
    const int col0 = nh * (DOUT / 2);

    int buf = 0;
    for (int tile = tile0; tile < nTiles; tile += gridDim.x) {
        int nextTile = tile + gridDim.x;
        if (nextTile < nTiles) {
            // issue next tile into other buffer
            for (int v = 0; v < 8; v++) {
                int idx = tid + v * 256;
                int rr  = idx >> 5;
                int kq  = (idx & 31) * 4;
                int gr  = nextTile * BM + rr;
                bool ok = (gr < n);
                const float* src = ok ? (A + (size_t)gr * K_DIM + kq) : A;
                cp_async16(smem_u32(&As[buf ^ 1][rr][kq]), src, ok ? 16 : 0);
            }
            cp_commit();
            cp_wait<1>();
        } else {
            cp_wait<0>();
        }
        __syncthreads();   // As[buf] ready (also covers W staging on first iter)

        const int row0 = tile * BM;

        // ---- both matmuls for this tile, sequential (keeps regs low) ----
#pragma unroll
        for (int wsel = 0; wsel < 2; wsel++) {
            float acc[NF][4];
#pragma unroll
            for (int f = 0; f < NF; f++)
#pragma unroll
                for (int j = 0; j < 4; j++) acc[f][j] = 0.f;

#pragma unroll
            for (int kstep = 0; kstep < K_DIM / 8; kstep++) {
                const int kb = kstep * 8;
                uint32_t a0 = f2tf(__uint_as_float(As[buf][wrow + g][kb + tig]));
                uint32_t a1 = f2tf(__uint_as_float(As[buf][wrow + g + 8][kb + tig]));
                uint32_t a2 = f2tf(__uint_as_float(As[buf][wrow + g][kb + tig + 4]));
                uint32_t a3 = f2tf(__uint_as_float(As[buf][wrow + g + 8][kb + tig + 4]));
#pragma unroll
                for (int f = 0; f < NF; f++) {
                    int col = col0 + f * 8 + g;
                    uint32_t b0 = Ws[wsel][kb + tig][col];
                    uint32_t b1 = Ws[wsel][kb + tig + 4][col];
                    mma_tf32(acc[f], a0, a1, a2, a3, b0, b1);
                }
            }

            float* C = wsel ? Cr : Cl;
            const int r_lo = row0 + wrow + g;
            const int r_hi = r_lo + 8;
#pragma unroll
            for (int f = 0; f < NF; f++) {
                int col = col0 + f * 8 + 2 * tig;
                float bv0 = wsel ? bias[col]     : 0.f;
                float bv1 = wsel ? bias[col + 1] : 0.f;
                if (r_lo < n)
                    *(float2*)(C + (size_t)r_lo * DOUT + col) =
                        make_float2(acc[f][0] + bv0, acc[f][1] + bv1);
                if (r_hi < n)
                    *(float2*)(C + (size_t)r_hi * DOUT + col) =
                        make_float2(acc[f][2] + bv0, acc[f][3] + bv1);
            }
        }

        __syncthreads();   // everyone done reading As[buf] before it is re-filled
        buf ^= 1;
    }
}

// ============================================================
// Aggregation + epilogue: out[n] = relu?( mean_{s in N(n)} xl[s] + xr[n] )
// One warp per destination node; coalesced index fetch + shfl broadcast;
// 8 row-gathers in flight.
// ============================================================
template <int DOUT, bool RELU>
__global__ __launch_bounds__(256) void agg_ep(
    const float* __restrict__ xl, const float* __restrict__ xr,
    float* __restrict__ out, int n)
{
    int gw   = (blockIdx.x * blockDim.x + threadIdx.x) >> 5;
    int lane = threadIdx.x & 31;
    if (gw >= n) return;

    int beg = g_rowptr[gw];
    int end = g_rowptr[gw + 1];
    float inv = 1.f / fmaxf((float)(end - beg), 1.f);

    if (DOUT == 128) {
        const float4* X = (const float4*)xl;
        float4 a0 = {0,0,0,0}, a1 = {0,0,0,0}, a2 = {0,0,0,0}, a3 = {0,0,0,0};
        for (int base = beg; base < end; base += 32) {
            int m = end - base; if (m > 32) m = 32;
            int p = base + lane; if (p >= end) p = end - 1;
            int idx = g_col[p];
            int j = 0;
            for (; j + 8 <= m; j += 8) {
                int s0 = __shfl_sync(0xffffffffu, idx, j + 0);
                int s1 = __shfl_sync(0xffffffffu, idx, j + 1);
                int s2 = __shfl_sync(0xffffffffu, idx, j + 2);
                int s3 = __shfl_sync(0xffffffffu, idx, j + 3);
                int s4 = __shfl_sync(0xffffffffu, idx, j + 4);
                int s5 = __shfl_sync(0xffffffffu, idx, j + 5);
                int s6 = __shfl_sync(0xffffffffu, idx, j + 6);
                int s7 = __shfl_sync(0xffffffffu, idx, j + 7);
                float4 v0 = X[s0 * 32 + lane];
                float4 v1 = X[s1 * 32 + lane];
                float4 v2 = X[s2 * 32 + lane];
                float4 v3 = X[s3 * 32 + lane];
                float4 v4 = X[s4 * 32 + lane];
                float4 v5 = X[s5 * 32 + lane];
                float4 v6 = X[s6 * 32 + lane];
                float4 v7 = X[s7 * 32 + lane];
                a0.x += v0.x; a0.y += v0.y; a0.z += v0.z; a0.w += v0.w;
                a1.x += v1.x; a1.y += v1.y; a1.z += v1.z; a1.w += v1.w;
                a2.x += v2.x; a2.y += v2.y; a2.z += v2.z; a2.w += v2.w;
                a3.x += v3.x; a3.y += v3.y; a3.z += v3.z; a3.w += v3.w;
                a0.x += v4.x; a0.y += v4.y; a0.z += v4.z; a0.w += v4.w;
                a1.x += v5.x; a1.y += v5.y; a1.z += v5.z; a1.w += v5.w;
                a2.x += v6.x; a2.y += v6.y; a2.z += v6.z; a2.w += v6.w;
                a3.x += v7.x; a3.y += v7.y; a3.z += v7.z; a3.w += v7.w;
            }
            for (; j < m; j++) {
                int s = __shfl_sync(0xffffffffu, idx, j);
                float4 v = X[s * 32 + lane];
                a0.x += v.x; a0.y += v.y; a0.z += v.z; a0.w += v.w;
            }
        }
        float4 r = ((const float4*)xr)[gw * 32 + lane];
        float4 o;
        o.x = (a0.x + a1.x + a2.x + a3.x) * inv + r.x;
        o.y = (a0.y + a1.y + a2.y + a3.y) * inv + r.y;
        o.z = (a0.z + a1.z + a2.z + a3.z) * inv + r.z;
        o.w = (a0.w + a1.w + a2.w + a3.w) * inv + r.w;
        if (RELU) {
            o.x = fmaxf(o.x, 0.f); o.y = fmaxf(o.y, 0.f);
            o.z = fmaxf(o.z, 0.f); o.w = fmaxf(o.w, 0.f);
        }
        ((float4*)out)[gw * 32 + lane] = o;
    } else {  // DOUT == 64, float2 per lane
        const float2* X = (const float2*)xl;
        float2 a0 = {0,0}, a1 = {0,0}, a2 = {0,0}, a3 = {0,0};
        for (int base = beg; base < end; base += 32) {
            int m = end - base; if (m > 32) m = 32;
            int p = base + lane; if (p >= end) p = end - 1;
            int idx = g_col[p];
            int j = 0;
            for (; j + 8 <= m; j += 8) {
                int s0 = __shfl_sync(0xffffffffu, idx, j + 0);
                int s1 = __shfl_sync(0xffffffffu, idx, j + 1);
                int s2 = __shfl_sync(0xffffffffu, idx, j + 2);
                int s3 = __shfl_sync(0xffffffffu, idx, j + 3);
                int s4 = __shfl_sync(0xffffffffu, idx, j + 4);
                int s5 = __shfl_sync(0xffffffffu, idx, j + 5);
                int s6 = __shfl_sync(0xffffffffu, idx, j + 6);
                int s7 = __shfl_sync(0xffffffffu, idx, j + 7);
                float2 v0 = X[s0 * 32 + lane];
                float2 v1 = X[s1 * 32 + lane];
                float2 v2 = X[s2 * 32 + lane];
                float2 v3 = X[s3 * 32 + lane];
                float2 v4 = X[s4 * 32 + lane];
                float2 v5 = X[s5 * 32 + lane];
                float2 v6 = X[s6 * 32 + lane];
                float2 v7 = X[s7 * 32 + lane];
                a0.x += v0.x; a0.y += v0.y;
                a1.x += v1.x; a1.y += v1.y;
                a2.x += v2.x; a2.y += v2.y;
                a3.x += v3.x; a3.y += v3.y;
                a0.x += v4.x; a0.y += v4.y;
                a1.x += v5.x; a1.y += v5.y;
                a2.x += v6.x; a2.y += v6.y;
                a3.x += v7.x; a3.y += v7.y;
            }
            for (; j < m; j++) {
                int s = __shfl_sync(0xffffffffu, idx, j);
                float2 v = X[s * 32 + lane];
                a0.x += v.x; a0.y += v.y;
            }
        }
        float2 r = ((const float2*)xr)[gw * 32 + lane];
        float2 o;
        o.x = (a0.x + a1.x + a2.x + a3.x) * inv + r.x;
        o.y = (a0.y + a1.y + a2.y + a3.y) * inv + r.y;
        if (RELU) { o.x = fmaxf(o.x, 0.f); o.y = fmaxf(o.y, 0.f); }
        ((float2*)out)[gw * 32 + lane] = o;
    }
}

// ============================================================
// Launch
// ============================================================
extern "C" void kernel_launch(void* const* d_in, const int* in_sizes, int n_in,
                              void* d_out, int out_size)
{
    const float* x   = (const float*)d_in[0];
    const int*   ei  = (const int*)d_in[1];
    const float* Wl0 = (const float*)d_in[2];
    const float* Wr0 = (const float*)d_in[3];
    const float* b0  = (const float*)d_in[4];
    const float* Wl1 = (const float*)d_in[5];
    const float* Wr1 = (const float*)d_in[6];
    const float* b1  = (const float*)d_in[7];
    const float* Wl2 = (const float*)d_in[8];
    const float* Wr2 = (const float*)d_in[9];
    const float* b2  = (const float*)d_in[10];

    const int n = in_sizes[0] / 128;
    const int e = in_sizes[1] / 2;
    const int* src = ei;
    const int* dst = ei + e;

    void *pxl, *pxr, *ph, *ph2, *pdeg;
    cudaGetSymbolAddress(&pxl, g_xl);
    cudaGetSymbolAddress(&pxr, g_xr);
    cudaGetSymbolAddress(&ph,  g_h);
    cudaGetSymbolAddress(&ph2, g_h2);
    cudaGetSymbolAddress(&pdeg, g_deg);
    float* f_xl = (float*)pxl;
    float* f_xr = (float*)pxr;
    float* f_h  = (float*)ph;
    float* f_h2 = (float*)ph2;

    // smem: Ws[2][128][DOUT+4] + As[2][64][132]
    constexpr int SM128 = (2 * 128 * 132 + 2 * 64 * 132) * 4;  // 202752 B
    constexpr int SM64  = (2 * 128 * 68  + 2 * 64 * 132) * 4;  // 137216 B

    static cudaStream_t s2 = nullptr;
    static cudaEvent_t evFork = nullptr, evJoin = nullptr;
    if (!s2) {
        cudaFuncSetAttribute(gemm_persist<128>, cudaFuncAttributeMaxDynamicSharedMemorySize, SM128);
        cudaFuncSetAttribute(gemm_persist<64>,  cudaFuncAttributeMaxDynamicSharedMemorySize, SM64);
        cudaStreamCreateWithFlags(&s2, cudaStreamNonBlocking);
        cudaEventCreateWithFlags(&evFork, cudaEventDisableTiming);
        cudaEventCreateWithFlags(&evJoin, cudaEventDisableTiming);
    }

    const int NSM = 148;
    const int agg_blocks = (n + 7) / 8;  // 8 warps/block, one warp per node

    // ---- fork: CSR build on s2, concurrent with layer-0 GEMM on stream 0 ----
    cudaEventRecord(evFork, 0);
    cudaStreamWaitEvent(s2, evFork, 0);
    cudaMemsetAsync(pdeg, 0, (size_t)n * sizeof(int), s2);
    hist_k<<<(e + 255) / 256, 256, 0, s2>>>(dst, e);
    scan_k<<<1, 1024, 0, s2>>>(n);
    scatter_k<<<(e + 255) / 256, 256, 0, s2>>>(src, dst, e);
    cudaEventRecord(evJoin, s2);

    // Layer 0 GEMM (stream 0, overlaps CSR build)
    gemm_persist<128><<<NSM, 256, SM128>>>(x, Wl0, Wr0, b0, f_xl, f_xr, n);

    // join: aggregation needs both CSR and gemm0
    cudaStreamWaitEvent(0, evJoin, 0);
    agg_ep<128, true><<<agg_blocks, 256>>>(f_xl, f_xr, f_h, n);

    // Layer 1
    gemm_persist<128><<<NSM, 256, SM128>>>(f_h, Wl1, Wr1, b1, f_xl, f_xr, n);
    agg_ep<128, true><<<agg_blocks, 256>>>(f_xl, f_xr, f_h2, n);

    // Layer 2 (DOUT=64, no relu) -> d_out
    gemm_persist<64><<<NSM, 256, SM64>>>(f_h2, Wl2, Wr2, b2, f_xl, f_xr, n);
    agg_ep<64, false><<<agg_blocks, 256>>>(f_xl, f_xr, (float*)d_out, n);
}

// round 6
// speedup vs baseline: 1.1045x; 1.1045x over previous
#include <cuda_runtime.h>
#include <cstdint>
#include <cstddef>

// Problem constants (match reference)
#define NMAX 100000
#define EMAX 1600000
#define K_DIM 128

// ---- Scratch (device globals; no allocations allowed) ----
__device__ int   g_deg[NMAX];
__device__ int   g_rowptr[NMAX + 1];
__device__ int   g_fill[NMAX];
__device__ int   g_col[EMAX];
__device__ float g_xl[(size_t)NMAX * 128];   // aggregated-path transform
__device__ float g_xr[(size_t)NMAX * 128];   // self-path transform (+bias)
__device__ float g_h[(size_t)NMAX * 128];    // layer-0 output
__device__ float g_h2[(size_t)NMAX * 128];   // layer-1 output

// ============================================================
// CSR build (counting sort by dst), rebuilt every launch
// ============================================================
__global__ void hist_k(const int* __restrict__ dst, int e) {
    int i = blockIdx.x * blockDim.x + threadIdx.x;
    if (i < e) atomicAdd(&g_deg[dst[i]], 1);
}

__global__ __launch_bounds__(1024) void scan_k(int n) {
    __shared__ int part[1024];
    int tid = threadIdx.x;
    int chunk = (n + 1023) >> 10;
    int beg = tid * chunk;
    int end = min(beg + chunk, n);
    int s = 0;
    for (int i = beg; i < end; i++) s += g_deg[i];
    part[tid] = s;
    __syncthreads();
    for (int off = 1; off < 1024; off <<= 1) {
        int v = (tid >= off) ? part[tid - off] : 0;
        __syncthreads();
        part[tid] += v;
        __syncthreads();
    }
    int base = part[tid] - s;  // exclusive prefix
    for (int i = beg; i < end; i++) {
        g_rowptr[i] = base;
        g_fill[i]   = base;
        base += g_deg[i];
    }
    if (tid == 1023) g_rowptr[n] = part[1023];
}

__global__ void scatter_k(const int* __restrict__ src, const int* __restrict__ dst, int e) {
    int i = blockIdx.x * blockDim.x + threadIdx.x;
    if (i < e) {
        int p = atomicAdd(&g_fill[dst[i]], 1);
        g_col[p] = src[i];
    }
}

// ============================================================
// tf32 / cp.async helpers
// ============================================================
__device__ __forceinline__ uint32_t f2tf(float x) {
    uint32_t u;
    asm("cvt.rna.tf32.f32 %0, %1;" : "=r"(u) : "f"(x));
    return u;
}

__device__ __forceinline__ void mma_tf32(
    float c[4], uint32_t a0, uint32_t a1, uint32_t a2, uint32_t a3,
    uint32_t b0, uint32_t b1)
{
    asm volatile(
        "mma.sync.aligned.m16n8k8.row.col.f32.tf32.tf32.f32 "
        "{%0,%1,%2,%3}, {%4,%5,%6,%7}, {%8,%9}, {%0,%1,%2,%3};"
        : "+f"(c[0]), "+f"(c[1]), "+f"(c[2]), "+f"(c[3])
        : "r"(a0), "r"(a1), "r"(a2), "r"(a3), "r"(b0), "r"(b1));
}

__device__ __forceinline__ uint32_t smem_u32(const void* p) {
    return (uint32_t)__cvta_generic_to_shared(p);
}

__device__ __forceinline__ void cp_async16(uint32_t dst, const void* src, int srcbytes) {
    asm volatile("cp.async.cg.shared.global [%0], [%1], 16, %2;"
                 :: "r"(dst), "l"(src), "r"(srcbytes));
}
__device__ __forceinline__ void cp_commit() {
    asm volatile("cp.async.commit_group;" ::: "memory");
}
template <int N>
__device__ __forceinline__ void cp_wait() {
    asm volatile("cp.async.wait_group %0;" :: "n"(N) : "memory");
}

// ============================================================
// Persistent dual GEMM (tf32 tensor cores), weights fully smem-resident:
//   Cl = A @ Wl ; Cr = A @ Wr + bias
// Grid = #SMs; each block stages Wl+Wr ONCE (tf32), then loops over strided
// 64-row A-tiles, double-buffered via cp.async.
// ============================================================
template <int DOUT>
__global__ __launch_bounds__(256) void gemm_persist(
    const float* __restrict__ A,
    const float* __restrict__ Wl, const float* __restrict__ Wr,
    const float* __restrict__ bias,
    float* __restrict__ Cl, float* __restrict__ Cr, int n)
{
    constexpr int BM = 64;
    constexpr int AS_STRIDE = K_DIM + 4;   // 132 (floats)
    constexpr int BS_STRIDE = DOUT + 4;
    constexpr int NF = DOUT / 16;          // n-frags per warp (half of DOUT / 8)

    extern __shared__ uint32_t smraw[];
    uint32_t (*Ws)[K_DIM][BS_STRIDE] = (uint32_t(*)[K_DIM][BS_STRIDE])smraw;
    uint32_t (*As)[BM][AS_STRIDE] =
        (uint32_t(*)[BM][AS_STRIDE])(smraw + 2 * K_DIM * BS_STRIDE);

    const int tid = threadIdx.x;
    const int nTiles = (n + BM - 1) / BM;

    // ---- issue cp.async for this block's first tile ----
    int tile0 = blockIdx.x;
    for (int v = 0; v < 8; v++) {
        int idx = tid + v * 256;
        int rr  = idx >> 5;
        int kq  = (idx & 31) * 4;
        int gr  = tile0 * BM + rr;
        bool ok = (tile0 < nTiles) && (gr < n);
        const float* src = ok ? (A + (size_t)gr * K_DIM + kq) : A;
        cp_async16(smem_u32(&As[0][rr][kq]), src, ok ? 16 : 0);
    }
    cp_commit();

    // ---- stage Wl, Wr once (tf32) ----
    constexpr int WV = (K_DIM * DOUT) / (4 * 256);
    for (int w = 0; w < 2; w++) {
        const float* W = w ? Wr : Wl;
#pragma unroll
        for (int v = 0; v < WV; v++) {
            int idx = tid + v * 256;
            int kk  = idx / (DOUT / 4);
            int c4  = (idx % (DOUT / 4)) * 4;
            float4 bv = *(const float4*)(W + (size_t)kk * DOUT + c4);
            uint4 uv;
            uv.x = f2tf(bv.x); uv.y = f2tf(bv.y);
            uv.z = f2tf(bv.z); uv.w = f2tf(bv.w);
            *(uint4*)&Ws[w][kk][c4] = uv;
        }
    }

    const int warp = tid >> 5;
    const int lane = tid & 31;
    const int g    = lane >> 2;
    const int tig  = lane & 3;
    const int rgrp = warp & 3;          // row group of 16
    const int nh   = warp >> 2;         // n half
    const int wrow = rgrp * 16;
    const int col0 = nh * (DOUT / 2);

    int buf = 0;
    for (int tile = tile0; tile < nTiles; tile += gridDim.x) {
        int nextTile = tile + gridDim.x;
        if (nextTile < nTiles) {
            for (int v = 0; v < 8; v++) {
                int idx = tid + v * 256;
                int rr  = idx >> 5;
                int kq  = (idx & 31) * 4;
                int gr  = nextTile * BM + rr;
                bool ok = (gr < n);
                const float* src = ok ? (A + (size_t)gr * K_DIM + kq) : A;
                cp_async16(smem_u32(&As[buf ^ 1][rr][kq]), src, ok ? 16 : 0);
            }
            cp_commit();
            cp_wait<1>();
        } else {
            cp_wait<0>();
        }
        __syncthreads();   // As[buf] ready (also covers W staging on first iter)

        const int row0 = tile * BM;

#pragma unroll
        for (int wsel = 0; wsel < 2; wsel++) {
            float acc[NF][4];
#pragma unroll
            for (int f = 0; f < NF; f++)
#pragma unroll
                for (int j = 0; j < 4; j++) acc[f][j] = 0.f;

#pragma unroll
            for (int kstep = 0; kstep < K_DIM / 8; kstep++) {
                const int kb = kstep * 8;
                uint32_t a0 = f2tf(__uint_as_float(As[buf][wrow + g][kb + tig]));
                uint32_t a1 = f2tf(__uint_as_float(As[buf][wrow + g + 8][kb + tig]));
                uint32_t a2 = f2tf(__uint_as_float(As[buf][wrow + g][kb + tig + 4]));
                uint32_t a3 = f2tf(__uint_as_float(As[buf][wrow + g + 8][kb + tig + 4]));
#pragma unroll
                for (int f = 0; f < NF; f++) {
                    int col = col0 + f * 8 + g;
                    uint32_t b0 = Ws[wsel][kb + tig][col];
                    uint32_t b1 = Ws[wsel][kb + tig + 4][col];
                    mma_tf32(acc[f], a0, a1, a2, a3, b0, b1);
                }
            }

            float* C = wsel ? Cr : Cl;
            const int r_lo = row0 + wrow + g;
            const int r_hi = r_lo + 8;
#pragma unroll
            for (int f = 0; f < NF; f++) {
                int col = col0 + f * 8 + 2 * tig;
                float bv0 = wsel ? bias[col]     : 0.f;
                float bv1 = wsel ? bias[col + 1] : 0.f;
                if (r_lo < n)
                    *(float2*)(C + (size_t)r_lo * DOUT + col) =
                        make_float2(acc[f][0] + bv0, acc[f][1] + bv1);
                if (r_hi < n)
                    *(float2*)(C + (size_t)r_hi * DOUT + col) =
                        make_float2(acc[f][2] + bv0, acc[f][3] + bv1);
            }
        }

        __syncthreads();
        buf ^= 1;
    }
}

// ============================================================
// Aggregation (DOUT=128): TWO warps per node, each owns 64 features
// (float2 per lane). Doubles warp-level MLP vs warp-per-node.
// ============================================================
template <bool RELU>
__global__ __launch_bounds__(256) void agg_ep128_split(
    const float* __restrict__ xl, const float* __restrict__ xr,
    float* __restrict__ out, int n)
{
    int gw2  = (blockIdx.x * blockDim.x + threadIdx.x) >> 5;
    int node = gw2 >> 1;
    int half = gw2 & 1;
    int lane = threadIdx.x & 31;
    if (node >= n) return;

    int beg = g_rowptr[node];
    int end = g_rowptr[node + 1];
    float inv = 1.f / fmaxf((float)(end - beg), 1.f);

    const float2* X = (const float2*)xl;   // row stride = 64 float2
    const int foff = half * 32 + lane;     // float2 index within row

    float2 a0 = {0,0}, a1 = {0,0}, a2 = {0,0}, a3 = {0,0};
    float2 a4 = {0,0}, a5 = {0,0}, a6 = {0,0}, a7 = {0,0};
    for (int base = beg; base < end; base += 32) {
        int m = end - base; if (m > 32) m = 32;
        int p = base + lane; if (p >= end) p = end - 1;
        int idx = g_col[p];
        int j = 0;
        for (; j + 8 <= m; j += 8) {
            int s0 = __shfl_sync(0xffffffffu, idx, j + 0);
            int s1 = __shfl_sync(0xffffffffu, idx, j + 1);
            int s2 = __shfl_sync(0xffffffffu, idx, j + 2);
            int s3 = __shfl_sync(0xffffffffu, idx, j + 3);
            int s4 = __shfl_sync(0xffffffffu, idx, j + 4);
            int s5 = __shfl_sync(0xffffffffu, idx, j + 5);
            int s6 = __shfl_sync(0xffffffffu, idx, j + 6);
            int s7 = __shfl_sync(0xffffffffu, idx, j + 7);
            float2 v0 = X[(size_t)s0 * 64 + foff];
            float2 v1 = X[(size_t)s1 * 64 + foff];
            float2 v2 = X[(size_t)s2 * 64 + foff];
            float2 v3 = X[(size_t)s3 * 64 + foff];
            float2 v4 = X[(size_t)s4 * 64 + foff];
            float2 v5 = X[(size_t)s5 * 64 + foff];
            float2 v6 = X[(size_t)s6 * 64 + foff];
            float2 v7 = X[(size_t)s7 * 64 + foff];
            a0.x += v0.x; a0.y += v0.y;
            a1.x += v1.x; a1.y += v1.y;
            a2.x += v2.x; a2.y += v2.y;
            a3.x += v3.x; a3.y += v3.y;
            a4.x += v4.x; a4.y += v4.y;
            a5.x += v5.x; a5.y += v5.y;
            a6.x += v6.x; a6.y += v6.y;
            a7.x += v7.x; a7.y += v7.y;
        }
        for (; j < m; j++) {
            int s = __shfl_sync(0xffffffffu, idx, j);
            float2 v = X[(size_t)s * 64 + foff];
            a0.x += v.x; a0.y += v.y;
        }
    }
    float2 r = ((const float2*)xr)[(size_t)node * 64 + foff];
    float2 o;
    o.x = ((a0.x + a1.x) + (a2.x + a3.x) + (a4.x + a5.x) + (a6.x + a7.x)) * inv + r.x;
    o.y = ((a0.y + a1.y) + (a2.y + a3.y) + (a4.y + a5.y) + (a6.y + a7.y)) * inv + r.y;
    if (RELU) { o.x = fmaxf(o.x, 0.f); o.y = fmaxf(o.y, 0.f); }
    ((float2*)out)[(size_t)node * 64 + foff] = o;
}

// ============================================================
// Aggregation (DOUT=64): one warp per node, float2 per lane.
// ============================================================
template <bool RELU>
__global__ __launch_bounds__(256) void agg_ep64(
    const float* __restrict__ xl, const float* __restrict__ xr,
    float* __restrict__ out, int n)
{
    int gw   = (blockIdx.x * blockDim.x + threadIdx.x) >> 5;
    int lane = threadIdx.x & 31;
    if (gw >= n) return;

    int beg = g_rowptr[gw];
    int end = g_rowptr[gw + 1];
    float inv = 1.f / fmaxf((float)(end - beg), 1.f);

    const float2* X = (const float2*)xl;
    float2 a0 = {0,0}, a1 = {0,0}, a2 = {0,0}, a3 = {0,0};
    float2 a4 = {0,0}, a5 = {0,0}, a6 = {0,0}, a7 = {0,0};
    for (int base = beg; base < end; base += 32) {
        int m = end - base; if (m > 32) m = 32;
        int p = base + lane; if (p >= end) p = end - 1;
        int idx = g_col[p];
        int j = 0;
        for (; j + 8 <= m; j += 8) {
            int s0 = __shfl_sync(0xffffffffu, idx, j + 0);
            int s1 = __shfl_sync(0xffffffffu, idx, j + 1);
            int s2 = __shfl_sync(0xffffffffu, idx, j + 2);
            int s3 = __shfl_sync(0xffffffffu, idx, j + 3);
            int s4 = __shfl_sync(0xffffffffu, idx, j + 4);
            int s5 = __shfl_sync(0xffffffffu, idx, j + 5);
            int s6 = __shfl_sync(0xffffffffu, idx, j + 6);
            int s7 = __shfl_sync(0xffffffffu, idx, j + 7);
            float2 v0 = X[(size_t)s0 * 32 + lane];
            float2 v1 = X[(size_t)s1 * 32 + lane];
            float2 v2 = X[(size_t)s2 * 32 + lane];
            float2 v3 = X[(size_t)s3 * 32 + lane];
            float2 v4 = X[(size_t)s4 * 32 + lane];
            float2 v5 = X[(size_t)s5 * 32 + lane];
            float2 v6 = X[(size_t)s6 * 32 + lane];
            float2 v7 = X[(size_t)s7 * 32 + lane];
            a0.x += v0.x; a0.y += v0.y;
            a1.x += v1.x; a1.y += v1.y;
            a2.x += v2.x; a2.y += v2.y;
            a3.x += v3.x; a3.y += v3.y;
            a4.x += v4.x; a4.y += v4.y;
            a5.x += v5.x; a5.y += v5.y;
            a6.x += v6.x; a6.y += v6.y;
            a7.x += v7.x; a7.y += v7.y;
        }
        for (; j < m; j++) {
            int s = __shfl_sync(0xffffffffu, idx, j);
            float2 v = X[(size_t)s * 32 + lane];
            a0.x += v.x; a0.y += v.y;
        }
    }
    float2 r = ((const float2*)xr)[(size_t)gw * 32 + lane];
    float2 o;
    o.x = ((a0.x + a1.x) + (a2.x + a3.x) + (a4.x + a5.x) + (a6.x + a7.x)) * inv + r.x;
    o.y = ((a0.y + a1.y) + (a2.y + a3.y) + (a4.y + a5.y) + (a6.y + a7.y)) * inv + r.y;
    if (RELU) { o.x = fmaxf(o.x, 0.f); o.y = fmaxf(o.y, 0.f); }
    ((float2*)out)[(size_t)gw * 32 + lane] = o;
}

// ============================================================
// Launch — single stream, CSR strictly before layer 0.
// ============================================================
extern "C" void kernel_launch(void* const* d_in, const int* in_sizes, int n_in,
                              void* d_out, int out_size)
{
    const float* x   = (const float*)d_in[0];
    const int*   ei  = (const int*)d_in[1];
    const float* Wl0 = (const float*)d_in[2];
    const float* Wr0 = (const float*)d_in[3];
    const float* b0  = (const float*)d_in[4];
    const float* Wl1 = (const float*)d_in[5];
    const float* Wr1 = (const float*)d_in[6];
    const float* b1  = (const float*)d_in[7];
    const float* Wl2 = (const float*)d_in[8];
    const float* Wr2 = (const float*)d_in[9];
    const float* b2  = (const float*)d_in[10];

    const int n = in_sizes[0] / 128;
    const int e = in_sizes[1] / 2;
    const int* src = ei;
    const int* dst = ei + e;

    void *pxl, *pxr, *ph, *ph2, *pdeg;
    cudaGetSymbolAddress(&pxl, g_xl);
    cudaGetSymbolAddress(&pxr, g_xr);
    cudaGetSymbolAddress(&ph,  g_h);
    cudaGetSymbolAddress(&ph2, g_h2);
    cudaGetSymbolAddress(&pdeg, g_deg);
    float* f_xl = (float*)pxl;
    float* f_xr = (float*)pxr;
    float* f_h  = (float*)ph;
    float* f_h2 = (float*)ph2;

    // smem: Ws[2][128][DOUT+4] + As[2][64][132]
    constexpr int SM128 = (2 * 128 * 132 + 2 * 64 * 132) * 4;  // 202752 B
    constexpr int SM64  = (2 * 128 * 68  + 2 * 64 * 132) * 4;  // 137216 B
    static bool attr_set = false;
    if (!attr_set) {
        cudaFuncSetAttribute(gemm_persist<128>, cudaFuncAttributeMaxDynamicSharedMemorySize, SM128);
        cudaFuncSetAttribute(gemm_persist<64>,  cudaFuncAttributeMaxDynamicSharedMemorySize, SM64);
        attr_set = true;
    }

    const int NSM = 148;
    const int agg128_blocks = (2 * n + 7) / 8;  // 2 warps per node, 8 warps/block
    const int agg64_blocks  = (n + 7) / 8;      // 1 warp per node

    // CSR build (single stream, before everything)
    cudaMemsetAsync(pdeg, 0, (size_t)n * sizeof(int));
    hist_k<<<(e + 255) / 256, 256>>>(dst, e);
    scan_k<<<1, 1024>>>(n);
    scatter_k<<<(e + 255) / 256, 256>>>(src, dst, e);

    // Layer 0: h = relu(mean_agg(x@Wl0) + x@Wr0 + b0)
    gemm_persist<128><<<NSM, 256, SM128>>>(x, Wl0, Wr0, b0, f_xl, f_xr, n);
    agg_ep128_split<true><<<agg128_blocks, 256>>>(f_xl, f_xr, f_h, n);

    // Layer 1
    gemm_persist<128><<<NSM, 256, SM128>>>(f_h, Wl1, Wr1, b1, f_xl, f_xr, n);
    agg_ep128_split<true><<<agg128_blocks, 256>>>(f_xl, f_xr, f_h2, n);

    // Layer 2 (DOUT=64, no relu) -> d_out
    gemm_persist<64><<<NSM, 256, SM64>>>(f_h2, Wl2, Wr2, b2, f_xl, f_xr, n);
    agg_ep64<false><<<agg64_blocks, 256>>>(f_xl, f_xr, (float*)d_out, n);
}

// round 7
// speedup vs baseline: 1.5659x; 1.4178x over previous
#include <cuda_runtime.h>
#include <cuda_fp16.h>
#include <cstdint>
#include <cstddef>

// Problem constants (match reference)
#define NMAX 100000
#define EMAX 1600000
#define K_DIM 128

// ---- Scratch (device globals; no allocations allowed) ----
__device__ int    g_deg[NMAX];
__device__ int    g_rowptr[NMAX + 1];
__device__ int    g_fill[NMAX];
__device__ int    g_col[EMAX];
__device__ __half g_xl[(size_t)NMAX * 128];   // aggregated-path transform (fp16)
__device__ float  g_xr[(size_t)NMAX * 128];   // self-path transform (+bias)
__device__ float  g_h[(size_t)NMAX * 128];    // layer-0 output
__device__ float  g_h2[(size_t)NMAX * 128];   // layer-1 output

// ============================================================
// CSR build (counting sort by dst), rebuilt every launch
// ============================================================
__global__ void hist_k(const int* __restrict__ dst, int e) {
    int i = blockIdx.x * blockDim.x + threadIdx.x;
    if (i < e) atomicAdd(&g_deg[dst[i]], 1);
}

__global__ __launch_bounds__(1024) void scan_k(int n) {
    __shared__ int part[1024];
    int tid = threadIdx.x;
    int chunk = (n + 1023) >> 10;
    int beg = tid * chunk;
    int end = min(beg + chunk, n);
    int s = 0;
    for (int i = beg; i < end; i++) s += g_deg[i];
    part[tid] = s;
    __syncthreads();
    for (int off = 1; off < 1024; off <<= 1) {
        int v = (tid >= off) ? part[tid - off] : 0;
        __syncthreads();
        part[tid] += v;
        __syncthreads();
    }
    int base = part[tid] - s;  // exclusive prefix
    for (int i = beg; i < end; i++) {
        g_rowptr[i] = base;
        g_fill[i]   = base;
        base += g_deg[i];
    }
    if (tid == 1023) g_rowptr[n] = part[1023];
}

__global__ void scatter_k(const int* __restrict__ src, const int* __restrict__ dst, int e) {
    int i = blockIdx.x * blockDim.x + threadIdx.x;
    if (i < e) {
        int p = atomicAdd(&g_fill[dst[i]], 1);
        g_col[p] = src[i];
    }
}

// ============================================================
// tf32 / cp.async helpers
// ============================================================
__device__ __forceinline__ uint32_t f2tf(float x) {
    uint32_t u;
    asm("cvt.rna.tf32.f32 %0, %1;" : "=r"(u) : "f"(x));
    return u;
}

__device__ __forceinline__ void mma_tf32(
    float c[4], uint32_t a0, uint32_t a1, uint32_t a2, uint32_t a3,
    uint32_t b0, uint32_t b1)
{
    asm volatile(
        "mma.sync.aligned.m16n8k8.row.col.f32.tf32.tf32.f32 "
        "{%0,%1,%2,%3}, {%4,%5,%6,%7}, {%8,%9}, {%0,%1,%2,%3};"
        : "+f"(c[0]), "+f"(c[1]), "+f"(c[2]), "+f"(c[3])
        : "r"(a0), "r"(a1), "r"(a2), "r"(a3), "r"(b0), "r"(b1));
}

__device__ __forceinline__ uint32_t smem_u32(const void* p) {
    return (uint32_t)__cvta_generic_to_shared(p);
}

__device__ __forceinline__ void cp_async16(uint32_t dst, const void* src, int srcbytes) {
    asm volatile("cp.async.cg.shared.global [%0], [%1], 16, %2;"
                 :: "r"(dst), "l"(src), "r"(srcbytes));
}
__device__ __forceinline__ void cp_commit() {
    asm volatile("cp.async.commit_group;" ::: "memory");
}
template <int N>
__device__ __forceinline__ void cp_wait() {
    asm volatile("cp.async.wait_group %0;" :: "n"(N) : "memory");
}

// ============================================================
// Persistent dual GEMM (tf32 tensor cores), weights fully smem-resident:
//   Cl = A @ Wl         (written as fp16 — feeds the mean-aggregation)
//   Cr = A @ Wr + bias  (fp32)
// Grid = #SMs; each block stages Wl+Wr ONCE (tf32), then loops over strided
// 64-row A-tiles, double-buffered via cp.async.
// ============================================================
template <int DOUT>
__global__ __launch_bounds__(256) void gemm_persist(
    const float* __restrict__ A,
    const float* __restrict__ Wl, const float* __restrict__ Wr,
    const float* __restrict__ bias,
    __half* __restrict__ Cl, float* __restrict__ Cr, int n)
{
    constexpr int BM = 64;
    constexpr int AS_STRIDE = K_DIM + 4;   // 132 (floats)
    constexpr int BS_STRIDE = DOUT + 4;
    constexpr int NF = DOUT / 16;          // n-frags per warp (half of DOUT / 8)

    extern __shared__ uint32_t smraw[];
    uint32_t (*Ws)[K_DIM][BS_STRIDE] = (uint32_t(*)[K_DIM][BS_STRIDE])smraw;
    uint32_t (*As)[BM][AS_STRIDE] =
        (uint32_t(*)[BM][AS_STRIDE])(smraw + 2 * K_DIM * BS_STRIDE);

    const int tid = threadIdx.x;
    const int nTiles = (n + BM - 1) / BM;

    // ---- issue cp.async for this block's first tile ----
    int tile0 = blockIdx.x;
    for (int v = 0; v < 8; v++) {
        int idx = tid + v * 256;
        int rr  = idx >> 5;
        int kq  = (idx & 31) * 4;
        int gr  = tile0 * BM + rr;
        bool ok = (tile0 < nTiles) && (gr < n);
        const float* src = ok ? (A + (size_t)gr * K_DIM + kq) : A;
        cp_async16(smem_u32(&As[0][rr][kq]), src, ok ? 16 : 0);
    }
    cp_commit();

    // ---- stage Wl, Wr once (tf32) ----
    constexpr int WV = (K_DIM * DOUT) / (4 * 256);
    for (int w = 0; w < 2; w++) {
        const float* W = w ? Wr : Wl;
#pragma unroll
        for (int v = 0; v < WV; v++) {
            int idx = tid + v * 256;
            int kk  = idx / (DOUT / 4);
            int c4  = (idx % (DOUT / 4)) * 4;
            float4 bv = *(const float4*)(W + (size_t)kk * DOUT + c4);
            uint4 uv;
            uv.x = f2tf(bv.x); uv.y = f2tf(bv.y);
            uv.z = f2tf(bv.z); uv.w = f2tf(bv.w);
            *(uint4*)&Ws[w][kk][c4] = uv;
        }
    }

    const int warp = tid >> 5;
    const int lane = tid & 31;
    const int g    = lane >> 2;
    const int tig  = lane & 3;
    const int rgrp = warp & 3;          // row group of 16
    const int nh   = warp >> 2;         // n half
    const int wrow = rgrp * 16;
    const int col0 = nh * (DOUT / 2);

    int buf = 0;
    for (int tile = tile0; tile < nTiles; tile += gridDim.x) {
        int nextTile = tile + gridDim.x;
        if (nextTile < nTiles) {
            for (int v = 0; v < 8; v++) {
                int idx = tid + v * 256;
                int rr  = idx >> 5;
                int kq  = (idx & 31) * 4;
                int gr  = nextTile * BM + rr;
                bool ok = (gr < n);
                const float* src = ok ? (A + (size_t)gr * K_DIM + kq) : A;
                cp_async16(smem_u32(&As[buf ^ 1][rr][kq]), src, ok ? 16 : 0);
            }
            cp_commit();
            cp_wait<1>();
        } else {
            cp_wait<0>();
        }
        __syncthreads();   // As[buf] ready (also covers W staging on first iter)

        const int row0 = tile * BM;

#pragma unroll
        for (int wsel = 0; wsel < 2; wsel++) {
            float acc[NF][4];
#pragma unroll
            for (int f = 0; f < NF; f++)
#pragma unroll
                for (int j = 0; j < 4; j++) acc[f][j] = 0.f;

#pragma unroll
            for (int kstep = 0; kstep < K_DIM / 8; kstep++) {
                const int kb = kstep * 8;
                uint32_t a0 = f2tf(__uint_as_float(As[buf][wrow + g][kb + tig]));
                uint32_t a1 = f2tf(__uint_as_float(As[buf][wrow + g + 8][kb + tig]));
                uint32_t a2 = f2tf(__uint_as_float(As[buf][wrow + g][kb + tig + 4]));
                uint32_t a3 = f2tf(__uint_as_float(As[buf][wrow + g + 8][kb + tig + 4]));
#pragma unroll
                for (int f = 0; f < NF; f++) {
                    int col = col0 + f * 8 + g;
                    uint32_t b0 = Ws[wsel][kb + tig][col];
                    uint32_t b1 = Ws[wsel][kb + tig + 4][col];
                    mma_tf32(acc[f], a0, a1, a2, a3, b0, b1);
                }
            }

            const int r_lo = row0 + wrow + g;
            const int r_hi = r_lo + 8;
            if (wsel == 0) {
                // Cl -> fp16
#pragma unroll
                for (int f = 0; f < NF; f++) {
                    int col = col0 + f * 8 + 2 * tig;
                    if (r_lo < n) {
                        __half2 h = __floats2half2_rn(acc[f][0], acc[f][1]);
                        *(__half2*)(Cl + (size_t)r_lo * DOUT + col) = h;
                    }
                    if (r_hi < n) {
                        __half2 h = __floats2half2_rn(acc[f][2], acc[f][3]);
                        *(__half2*)(Cl + (size_t)r_hi * DOUT + col) = h;
                    }
                }
            } else {
                // Cr -> fp32 (+bias)
#pragma unroll
                for (int f = 0; f < NF; f++) {
                    int col = col0 + f * 8 + 2 * tig;
                    float bv0 = bias[col];
                    float bv1 = bias[col + 1];
                    if (r_lo < n)
                        *(float2*)(Cr + (size_t)r_lo * DOUT + col) =
                            make_float2(acc[f][0] + bv0, acc[f][1] + bv1);
                    if (r_hi < n)
                        *(float2*)(Cr + (size_t)r_hi * DOUT + col) =
                            make_float2(acc[f][2] + bv0, acc[f][3] + bv1);
                }
            }
        }

        __syncthreads();
        buf ^= 1;
    }
}

// ============================================================
// Aggregation + epilogue: out = relu?( mean_{s in N(n)} xl[s] + xr[n] )
// xl is fp16. One warp per node; serial index loads; 8 gathers in flight.
// DOUT=128: lane owns 4 features (uint2 = 2 x half2, 8B; warp = 256B/row).
// ============================================================
template <bool RELU>
__global__ __launch_bounds__(256) void agg_ep128h(
    const __half* __restrict__ xl, const float* __restrict__ xr,
    float* __restrict__ out, int n)
{
    int gw   = (blockIdx.x * blockDim.x + threadIdx.x) >> 5;
    int lane = threadIdx.x & 31;
    if (gw >= n) return;

    int beg = g_rowptr[gw];
    int end = g_rowptr[gw + 1];
    float inv = 1.f / fmaxf((float)(end - beg), 1.f);

    const uint2* X = (const uint2*)xl;   // row = 32 uint2
    float ax = 0.f, ay = 0.f, az = 0.f, aw = 0.f;
    float bx = 0.f, by = 0.f, bz = 0.f, bw = 0.f;

    int e = beg;
    for (; e + 8 <= end; e += 8) {
        int s0 = g_col[e + 0], s1 = g_col[e + 1], s2 = g_col[e + 2], s3 = g_col[e + 3];
        int s4 = g_col[e + 4], s5 = g_col[e + 5], s6 = g_col[e + 6], s7 = g_col[e + 7];
        uint2 v0 = X[(size_t)s0 * 32 + lane];
        uint2 v1 = X[(size_t)s1 * 32 + lane];
        uint2 v2 = X[(size_t)s2 * 32 + lane];
        uint2 v3 = X[(size_t)s3 * 32 + lane];
        uint2 v4 = X[(size_t)s4 * 32 + lane];
        uint2 v5 = X[(size_t)s5 * 32 + lane];
        uint2 v6 = X[(size_t)s6 * 32 + lane];
        uint2 v7 = X[(size_t)s7 * 32 + lane];
        float2 f;
        f = __half22float2(*(__half2*)&v0.x); ax += f.x; ay += f.y;
        f = __half22float2(*(__half2*)&v0.y); az += f.x; aw += f.y;
        f = __half22float2(*(__half2*)&v1.x); bx += f.x; by += f.y;
        f = __half22float2(*(__half2*)&v1.y); bz += f.x; bw += f.y;
        f = __half22float2(*(__half2*)&v2.x); ax += f.x; ay += f.y;
        f = __half22float2(*(__half2*)&v2.y); az += f.x; aw += f.y;
        f = __half22float2(*(__half2*)&v3.x); bx += f.x; by += f.y;
        f = __half22float2(*(__half2*)&v3.y); bz += f.x; bw += f.y;
        f = __half22float2(*(__half2*)&v4.x); ax += f.x; ay += f.y;
        f = __half22float2(*(__half2*)&v4.y); az += f.x; aw += f.y;
        f = __half22float2(*(__half2*)&v5.x); bx += f.x; by += f.y;
        f = __half22float2(*(__half2*)&v5.y); bz += f.x; bw += f.y;
        f = __half22float2(*(__half2*)&v6.x); ax += f.x; ay += f.y;
        f = __half22float2(*(__half2*)&v6.y); az += f.x; aw += f.y;
        f = __half22float2(*(__half2*)&v7.x); bx += f.x; by += f.y;
        f = __half22float2(*(__half2*)&v7.y); bz += f.x; bw += f.y;
    }
    for (; e < end; e++) {
        int s = g_col[e];
        uint2 v = X[(size_t)s * 32 + lane];
        float2 f;
        f = __half22float2(*(__half2*)&v.x); ax += f.x; ay += f.y;
        f = __half22float2(*(__half2*)&v.y); az += f.x; aw += f.y;
    }

    float4 r = ((const float4*)xr)[(size_t)gw * 32 + lane];
    float4 o;
    o.x = (ax + bx) * inv + r.x;
    o.y = (ay + by) * inv + r.y;
    o.z = (az + bz) * inv + r.z;
    o.w = (aw + bw) * inv + r.w;
    if (RELU) {
        o.x = fmaxf(o.x, 0.f); o.y = fmaxf(o.y, 0.f);
        o.z = fmaxf(o.z, 0.f); o.w = fmaxf(o.w, 0.f);
    }
    ((float4*)out)[(size_t)gw * 32 + lane] = o;
}

// DOUT=64: lane owns 2 features (half2 = 4B; warp = 128B/row).
template <bool RELU>
__global__ __launch_bounds__(256) void agg_ep64h(
    const __half* __restrict__ xl, const float* __restrict__ xr,
    float* __restrict__ out, int n)
{
    int gw   = (blockIdx.x * blockDim.x + threadIdx.x) >> 5;
    int lane = threadIdx.x & 31;
    if (gw >= n) return;

    int beg = g_rowptr[gw];
    int end = g_rowptr[gw + 1];
    float inv = 1.f / fmaxf((float)(end - beg), 1.f);

    const uint32_t* X = (const uint32_t*)xl;  // row = 32 half2
    float ax = 0.f, ay = 0.f, bx = 0.f, by = 0.f;

    int e = beg;
    for (; e + 8 <= end; e += 8) {
        int s0 = g_col[e + 0], s1 = g_col[e + 1], s2 = g_col[e + 2], s3 = g_col[e + 3];
        int s4 = g_col[e + 4], s5 = g_col[e + 5], s6 = g_col[e + 6], s7 = g_col[e + 7];
        uint32_t v0 = X[(size_t)s0 * 32 + lane];
        uint32_t v1 = X[(size_t)s1 * 32 + lane];
        uint32_t v2 = X[(size_t)s2 * 32 + lane];
        uint32_t v3 = X[(size_t)s3 * 32 + lane];
        uint32_t v4 = X[(size_t)s4 * 32 + lane];
        uint32_t v5 = X[(size_t)s5 * 32 + lane];
        uint32_t v6 = X[(size_t)s6 * 32 + lane];
        uint32_t v7 = X[(size_t)s7 * 32 + lane];
        float2 f;
        f = __half22float2(*(__half2*)&v0); ax += f.x; ay += f.y;
        f = __half22float2(*(__half2*)&v1); bx += f.x; by += f.y;
        f = __half22float2(*(__half2*)&v2); ax += f.x; ay += f.y;
        f = __half22float2(*(__half2*)&v3); bx += f.x; by += f.y;
        f = __half22float2(*(__half2*)&v4); ax += f.x; ay += f.y;
        f = __half22float2(*(__half2*)&v5); bx += f.x; by += f.y;
        f = __half22float2(*(__half2*)&v6); ax += f.x; ay += f.y;
        f = __half22float2(*(__half2*)&v7); bx += f.x; by += f.y;
    }
    for (; e < end; e++) {
        int s = g_col[e];
        uint32_t v = X[(size_t)s * 32 + lane];
        float2 f = __half22float2(*(__half2*)&v);
        ax += f.x; ay += f.y;
    }

    float2 r = ((const float2*)xr)[(size_t)gw * 32 + lane];
    float2 o;
    o.x = (ax + bx) * inv + r.x;
    o.y = (ay + by) * inv + r.y;
    if (RELU) { o.x = fmaxf(o.x, 0.f); o.y = fmaxf(o.y, 0.f); }
    ((float2*)out)[(size_t)gw * 32 + lane] = o;
}

// ============================================================
// Launch — single stream, CSR strictly before layer 0.
// ============================================================
extern "C" void kernel_launch(void* const* d_in, const int* in_sizes, int n_in,
                              void* d_out, int out_size)
{
    const float* x   = (const float*)d_in[0];
    const int*   ei  = (const int*)d_in[1];
    const float* Wl0 = (const float*)d_in[2];
    const float* Wr0 = (const float*)d_in[3];
    const float* b0  = (const float*)d_in[4];
    const float* Wl1 = (const float*)d_in[5];
    const float* Wr1 = (const float*)d_in[6];
    const float* b1  = (const float*)d_in[7];
    const float* Wl2 = (const float*)d_in[8];
    const float* Wr2 = (const float*)d_in[9];
    const float* b2  = (const float*)d_in[10];

    const int n = in_sizes[0] / 128;
    const int e = in_sizes[1] / 2;
    const int* src = ei;
    const int* dst = ei + e;

    void *pxl, *pxr, *ph, *ph2, *pdeg;
    cudaGetSymbolAddress(&pxl, g_xl);
    cudaGetSymbolAddress(&pxr, g_xr);
    cudaGetSymbolAddress(&ph,  g_h);
    cudaGetSymbolAddress(&ph2, g_h2);
    cudaGetSymbolAddress(&pdeg, g_deg);
    __half* f_xl = (__half*)pxl;
    float*  f_xr = (float*)pxr;
    float*  f_h  = (float*)ph;
    float*  f_h2 = (float*)ph2;

    // smem: Ws[2][128][DOUT+4] + As[2][64][132]
    constexpr int SM128 = (2 * 128 * 132 + 2 * 64 * 132) * 4;  // 202752 B
    constexpr int SM64  = (2 * 128 * 68  + 2 * 64 * 132) * 4;  // 137216 B
    static bool attr_set = false;
    if (!attr_set) {
        cudaFuncSetAttribute(gemm_persist<128>, cudaFuncAttributeMaxDynamicSharedMemorySize, SM128);
        cudaFuncSetAttribute(gemm_persist<64>,  cudaFuncAttributeMaxDynamicSharedMemorySize, SM64);
        attr_set = true;
    }

    const int NSM = 148;
    const int agg_blocks = (n + 7) / 8;  // 8 warps/block, one warp per node

    // CSR build (single stream, before everything)
    cudaMemsetAsync(pdeg, 0, (size_t)n * sizeof(int));
    hist_k<<<(e + 255) / 256, 256>>>(dst, e);
    scan_k<<<1, 1024>>>(n);
    scatter_k<<<(e + 255) / 256, 256>>>(src, dst, e);

    // Layer 0: h = relu(mean_agg(x@Wl0) + x@Wr0 + b0)
    gemm_persist<128><<<NSM, 256, SM128>>>(x, Wl0, Wr0, b0, f_xl, f_xr, n);
    agg_ep128h<true><<<agg_blocks, 256>>>(f_xl, f_xr, f_h, n);

    // Layer 1
    gemm_persist<128><<<NSM, 256, SM128>>>(f_h, Wl1, Wr1, b1, f_xl, f_xr, n);
    agg_ep128h<true><<<agg_blocks, 256>>>(f_xl, f_xr, f_h2, n);

    // Layer 2 (DOUT=64, no relu) -> d_out
    gemm_persist<64><<<NSM, 256, SM64>>>(f_h2, Wl2, Wr2, b2, f_xl, f_xr, n);
    agg_ep64h<false><<<agg_blocks, 256>>>(f_xl, f_xr, (float*)d_out, n);
}